// round 1
// baseline (speedup 1.0000x reference)
#include <cuda_runtime.h>
#include <cuda_bf16.h>

// Problem constants (fixed shapes from reference setup_inputs)
#define BB 4
#define NN 3137          // 1 + 16*196
#define DIM 1024
#define HH 16
#define HD 64
#define FF 16
#define NS 196
#define BH (BB*HH)       // 64
#define M_TOT (BB*NN)    // 12548
#define QSCALE 0.125f    // 64^-0.5

// Scratch in device globals (no allocations allowed)
__device__ float g_q[(size_t)BH * NN * HD];      // head-major, pre-scaled
__device__ float g_k[(size_t)BH * NN * HD];
__device__ float g_v[(size_t)BH * NN * HD];
__device__ float g_attn[(size_t)BB * NN * DIM];  // (B, N, H*HD) assembled attention output

// ---------------------------------------------------------------------------
// Tiled SGEMM: C[m,n] = sum_k A[m,k] * W[n,k] + bias[n]
// MODE 0: A = x, epilogue scatters into g_q/g_k/g_v head-major (+scale on q)
// MODE 1: A = g_attn (global), epilogue writes Cout[m*Nn+n]
// Tile: BM=BN=128, BK=16, 256 threads, 8x8 per thread.
// ---------------------------------------------------------------------------
template <int MODE>
__global__ void __launch_bounds__(256, 2)
gemm_kernel(const float* __restrict__ A, const float* __restrict__ Bw,
            const float* __restrict__ bias, float* __restrict__ Cout,
            int M, int Nn, int K)
{
    __shared__ float As[16 * 128];
    __shared__ float Bs[16 * 128];

    const int n0 = blockIdx.x * 128;
    const int m0 = blockIdx.y * 128;
    const int tid = threadIdx.x;
    const int tx = tid & 15;       // 0..15 -> n
    const int ty = tid >> 4;       // 0..15 -> m

    const float* Aptr = (MODE == 1) ? g_attn : A;

    const int lr = tid >> 2;       // 0..63
    const int lc = (tid & 3) * 4;  // 0,4,8,12

    float acc[8][8];
#pragma unroll
    for (int i = 0; i < 8; i++)
#pragma unroll
        for (int j = 0; j < 8; j++) acc[i][j] = 0.f;

    for (int k0 = 0; k0 < K; k0 += 16) {
#pragma unroll
        for (int rr = 0; rr < 128; rr += 64) {
            const int r = lr + rr;
            // A tile (guard M edge)
            const int gm = m0 + r;
            float4 va = make_float4(0.f, 0.f, 0.f, 0.f);
            if (gm < M) va = *(const float4*)&Aptr[(size_t)gm * K + k0 + lc];
            As[(lc + 0) * 128 + r] = va.x;
            As[(lc + 1) * 128 + r] = va.y;
            As[(lc + 2) * 128 + r] = va.z;
            As[(lc + 3) * 128 + r] = va.w;
            // W tile (Nn always a multiple of 128)
            const int gn = n0 + r;
            float4 vb = *(const float4*)&Bw[(size_t)gn * K + k0 + lc];
            Bs[(lc + 0) * 128 + r] = vb.x;
            Bs[(lc + 1) * 128 + r] = vb.y;
            Bs[(lc + 2) * 128 + r] = vb.z;
            Bs[(lc + 3) * 128 + r] = vb.w;
        }
        __syncthreads();

#pragma unroll
        for (int k = 0; k < 16; k++) {
            float a[8], b[8];
            *(float4*)&a[0] = *(const float4*)&As[k * 128 + ty * 8];
            *(float4*)&a[4] = *(const float4*)&As[k * 128 + ty * 8 + 4];
            *(float4*)&b[0] = *(const float4*)&Bs[k * 128 + tx * 8];
            *(float4*)&b[4] = *(const float4*)&Bs[k * 128 + tx * 8 + 4];
#pragma unroll
            for (int i = 0; i < 8; i++)
#pragma unroll
                for (int j = 0; j < 8; j++)
                    acc[i][j] = fmaf(a[i], b[j], acc[i][j]);
        }
        __syncthreads();
    }

    // Epilogue
#pragma unroll
    for (int i = 0; i < 8; i++) {
        const int m = m0 + ty * 8 + i;
        if (m >= M) continue;
        if (MODE == 1) {
#pragma unroll
            for (int j = 0; j < 8; j++) {
                const int n = n0 + tx * 8 + j;
                Cout[(size_t)m * Nn + n] = acc[i][j] + bias[n];
            }
        } else {
            const int b_idx = m / NN;
            const int itok = m - b_idx * NN;
#pragma unroll
            for (int j = 0; j < 8; j++) {
                const int n = n0 + tx * 8 + j;
                const float val = acc[i][j] + bias[n];
                const int which = n >> 10;      // 0=q 1=k 2=v
                const int c = n & 1023;
                const int h = c >> 6;
                const int d = c & 63;
                const size_t dst = ((size_t)(b_idx * HH + h)) * NN * HD
                                 + (size_t)itok * HD + d;
                if (which == 0)      g_q[dst] = val * QSCALE;
                else if (which == 1) g_k[dst] = val;
                else                 g_v[dst] = val;
            }
        }
    }
}

// ---------------------------------------------------------------------------
// cls-token attention: one block per (b,h). q row 0 attends to all N keys.
// ---------------------------------------------------------------------------
__global__ void __launch_bounds__(256)
cls_attn_kernel(const int* __restrict__ tok_mask)
{
    __shared__ float qs[64];
    __shared__ float p[NN];
    __shared__ float red[256];
    __shared__ float part[4 * 64];

    const int bh = blockIdx.x;
    const int b = bh >> 4, h = bh & 15;
    const int tid = threadIdx.x;
    const size_t base = (size_t)bh * NN * HD;

    if (tid < 64) qs[tid] = g_q[base + tid];
    __syncthreads();

    float mx = -1e30f;
    for (int j = tid; j < NN; j += 256) {
        const float* kr = &g_k[base + (size_t)j * HD];
        float acc = 0.f;
#pragma unroll
        for (int d = 0; d < 64; d++) acc = fmaf(qs[d], kr[d], acc);
        if (!tok_mask[b * NN + j]) acc = -1e30f;
        p[j] = acc;
        mx = fmaxf(mx, acc);
    }
    red[tid] = mx;
    __syncthreads();
    for (int s = 128; s; s >>= 1) {
        if (tid < s) red[tid] = fmaxf(red[tid], red[tid + s]);
        __syncthreads();
    }
    mx = red[0];
    __syncthreads();   // everyone has read red[0] before it is rewritten

    float sum = 0.f;
    for (int j = tid; j < NN; j += 256) {
        const float e = __expf(p[j] - mx);
        p[j] = e;
        sum += e;
    }
    red[tid] = sum;
    __syncthreads();
    for (int s = 128; s; s >>= 1) {
        if (tid < s) red[tid] += red[tid + s];
        __syncthreads();
    }
    const float inv = 1.f / red[0];

    const int pt = tid >> 6;      // 0..3
    const int d = tid & 63;
    float acc = 0.f;
    for (int j = pt; j < NN; j += 4)
        acc = fmaf(p[j], g_v[base + (size_t)j * HD + d], acc);
    part[pt * 64 + d] = acc;
    __syncthreads();
    if (tid < 64) {
        const float o = (part[tid] + part[64 + tid] + part[128 + tid] + part[192 + tid]) * inv;
        g_attn[(size_t)b * NN * DIM + (size_t)h * HD + tid] = o;
    }
}

// ---------------------------------------------------------------------------
// Divided (spatial) attention: grid (1024 groups, 7 query chunks of 32).
// Per group: Q chunk (<=32 x 64), K/V (197 x 64) staged in padded smem.
// ---------------------------------------------------------------------------
#define DIV_SMEM_FLOATS (32*64 + 2*197*65 + 32*197 + 197)
#define DIV_SMEM_BYTES  (DIV_SMEM_FLOATS * 4)

__global__ void __launch_bounds__(256)
divided_attn_kernel(const int* __restrict__ tok_mask)
{
    extern __shared__ float sm[];
    float* Qs = sm;                    // 32*64
    float* Ks = Qs + 32 * 64;          // 197*65 (padded)
    float* Vs = Ks + 197 * 65;         // 197*65 (padded)
    float* S  = Vs + 197 * 65;         // 32*197
    float* Ms = S + 32 * 197;          // 197 additive mask

    const int g = blockIdx.x;
    const int bh = g >> 4;
    const int fi = g & 15;
    const int b = bh >> 4;
    const int h = bh & 15;
    const int i0 = blockIdx.y * 32;
    const int cnt = min(32, NS - i0);
    const int tid = threadIdx.x;

    const size_t base = (size_t)bh * NN * HD;
    const int tq0 = 1 + fi * NS + i0;

    for (int idx = tid; idx < cnt * 64; idx += 256) {
        const int i = idx >> 6, d = idx & 63;
        Qs[idx] = g_q[base + (size_t)(tq0 + i) * HD + d];
    }
    for (int idx = tid; idx < 197 * 64; idx += 256) {
        const int j = idx >> 6, d = idx & 63;
        const int tk = (j == 0) ? 0 : (1 + fi * NS + j - 1);
        Ks[j * 65 + d] = g_k[base + (size_t)tk * HD + d];
        Vs[j * 65 + d] = g_v[base + (size_t)tk * HD + d];
    }
    for (int j = tid; j < 197; j += 256) {
        const int tk = (j == 0) ? 0 : (1 + fi * NS + j - 1);
        Ms[j] = tok_mask[b * NN + tk] ? 0.f : -1e30f;
    }
    __syncthreads();

    // S = Q K^T (+mask); thread-parallel over (i,j)
    for (int idx = tid; idx < cnt * 197; idx += 256) {
        const int i = idx / 197;
        const int j = idx - i * 197;
        const float* qr = Qs + i * 64;
        const float* kr = Ks + j * 65;
        float acc = 0.f;
#pragma unroll
        for (int d = 0; d < 64; d++) acc = fmaf(qr[d], kr[d], acc);
        S[idx] = acc + Ms[j];
    }
    __syncthreads();

    // row softmax: warp w handles rows w, w+8, ...
    const int w = tid >> 5, lane = tid & 31;
    for (int r = w; r < cnt; r += 8) {
        float* row = S + r * 197;
        float mx = -1e30f;
        for (int j = lane; j < 197; j += 32) mx = fmaxf(mx, row[j]);
        for (int o = 16; o; o >>= 1) mx = fmaxf(mx, __shfl_xor_sync(~0u, mx, o));
        float sum = 0.f;
        for (int j = lane; j < 197; j += 32) {
            const float e = __expf(row[j] - mx);
            row[j] = e;
            sum += e;
        }
        for (int o = 16; o; o >>= 1) sum += __shfl_xor_sync(~0u, sum, o);
        const float inv = 1.f / sum;
        for (int j = lane; j < 197; j += 32) row[j] *= inv;
    }
    __syncthreads();

    // O = P V; write directly into assembled (B, N, DIM) layout
    for (int idx = tid; idx < cnt * 64; idx += 256) {
        const int i = idx >> 6, d = idx & 63;
        const float* pr = S + i * 197;
        const float* vc = Vs + d;
        float acc = 0.f;
#pragma unroll 4
        for (int j = 0; j < 197; j++) acc = fmaf(pr[j], vc[j * 65], acc);
        g_attn[(size_t)b * NN * DIM + (size_t)(tq0 + i) * DIM + h * HD + d] = acc;
    }
}

// ---------------------------------------------------------------------------
extern "C" void kernel_launch(void* const* d_in, const int* in_sizes, int n_in,
                              void* d_out, int out_size)
{
    const float* x      = (const float*)d_in[0];
    const float* qkv_w  = (const float*)d_in[1];
    const float* qkv_b  = (const float*)d_in[2];
    const float* proj_w = (const float*)d_in[3];
    const float* proj_b = (const float*)d_in[4];
    const int*   tmask  = (const int*)d_in[5];
    float* out = (float*)d_out;

    cudaFuncSetAttribute((const void*)divided_attn_kernel,
                         cudaFuncAttributeMaxDynamicSharedMemorySize, DIV_SMEM_BYTES);

    // 1) QKV GEMM (epilogue scatters into head-major q/k/v, q scaled)
    gemm_kernel<0><<<dim3(3 * DIM / 128, (M_TOT + 127) / 128), 256>>>(
        x, qkv_w, qkv_b, nullptr, M_TOT, 3 * DIM, DIM);

    // 2) cls attention (64 head-batches)
    cls_attn_kernel<<<BH, 256>>>(tmask);

    // 3) divided spatial attention (1024 groups x 7 query chunks)
    divided_attn_kernel<<<dim3(BH * FF, (NS + 31) / 32), 256, DIV_SMEM_BYTES>>>(tmask);

    // 4) output projection GEMM
    gemm_kernel<1><<<dim3(DIM / 128, (M_TOT + 127) / 128), 256>>>(
        nullptr, proj_w, proj_b, out, M_TOT, DIM, DIM);
}

// round 2
// speedup vs baseline: 1.5947x; 1.5947x over previous
#include <cuda_runtime.h>
#include <cuda_bf16.h>
#include <cstdint>

// Problem constants (fixed shapes from reference setup_inputs)
#define BB 4
#define NN 3137          // 1 + 16*196
#define DIM 1024
#define HH 16
#define HD 64
#define FF 16
#define NS 196
#define BH (BB*HH)       // 64
#define M_TOT (BB*NN)    // 12548
#define QSCALE 0.125f    // 64^-0.5

// Scratch in device globals (no allocations allowed)
__device__ float g_q[(size_t)BH * NN * HD];      // head-major, pre-scaled
__device__ float g_k[(size_t)BH * NN * HD];
__device__ float g_v[(size_t)BH * NN * HD];
__device__ float g_attn[(size_t)BB * NN * DIM];  // (B, N, H*HD) assembled attention output

__device__ __forceinline__ uint32_t f2tf32(float f) {
    uint32_t r;
    asm("cvt.rna.tf32.f32 %0, %1;" : "=r"(r) : "f"(f));
    return r;
}

__device__ __forceinline__ void mma_tf32(float4& c, const uint32_t a[4], const uint32_t b[2]) {
    asm volatile(
        "mma.sync.aligned.m16n8k8.row.col.f32.tf32.tf32.f32 "
        "{%0,%1,%2,%3}, {%4,%5,%6,%7}, {%8,%9}, {%0,%1,%2,%3};"
        : "+f"(c.x), "+f"(c.y), "+f"(c.z), "+f"(c.w)
        : "r"(a[0]), "r"(a[1]), "r"(a[2]), "r"(a[3]), "r"(b[0]), "r"(b[1]));
}

// ---------------------------------------------------------------------------
// TF32 tensor-core GEMM: C[m,n] = sum_k A[m,k] * W[n,k] + bias[n]
// MODE 0: A = x, epilogue scatters into g_q/g_k/g_v head-major (+scale on q)
// MODE 1: A = g_attn (global), epilogue writes Cout[m*Nn+n]
// Tile: BM=BN=128, BK=32, 256 threads (8 warps, 4x2 of 32x64 warp tiles).
// Smem stride 36 -> conflict-free fragment LDS and float4 STS.
// ---------------------------------------------------------------------------
template <int MODE>
__global__ void __launch_bounds__(256, 2)
gemm_tf32_kernel(const float* __restrict__ A, const float* __restrict__ Bw,
                 const float* __restrict__ bias, float* __restrict__ Cout,
                 int M, int Nn, int K)
{
    __shared__ float As[128 * 36];
    __shared__ float Bs[128 * 36];

    const int n0 = blockIdx.x * 128;
    const int m0 = blockIdx.y * 128;
    const int tid = threadIdx.x;
    const int warp = tid >> 5;
    const int lane = tid & 31;
    const int grp = lane >> 2;     // 0..7
    const int qid = lane & 3;      // 0..3
    const int wm = warp & 3;       // 0..3 -> m offset 32*wm
    const int wn = warp >> 2;      // 0..1 -> n offset 64*wn

    const float* Aptr = (MODE == 1) ? g_attn : A;

    const int lr = tid >> 3;       // 0..31
    const int lc = (tid & 7) * 4;  // 0,4,...,28

    float4 acc[2][8];
#pragma unroll
    for (int i = 0; i < 2; i++)
#pragma unroll
        for (int j = 0; j < 8; j++) acc[i][j] = make_float4(0.f, 0.f, 0.f, 0.f);

    for (int k0 = 0; k0 < K; k0 += 32) {
        // global -> (cvt tf32) -> smem
#pragma unroll
        for (int i = 0; i < 4; i++) {
            const int r = lr + i * 32;
            const int gm = m0 + r;
            float4 va = make_float4(0.f, 0.f, 0.f, 0.f);
            if (gm < M) va = *(const float4*)&Aptr[(size_t)gm * K + k0 + lc];
            uint32_t* dstA = (uint32_t*)&As[r * 36 + lc];
            ((uint4*)dstA)[0] = make_uint4(f2tf32(va.x), f2tf32(va.y), f2tf32(va.z), f2tf32(va.w));

            const int gn = n0 + r;
            float4 vb = *(const float4*)&Bw[(size_t)gn * K + k0 + lc];
            uint32_t* dstB = (uint32_t*)&Bs[r * 36 + lc];
            ((uint4*)dstB)[0] = make_uint4(f2tf32(vb.x), f2tf32(vb.y), f2tf32(vb.z), f2tf32(vb.w));
        }
        __syncthreads();

#pragma unroll
        for (int kk = 0; kk < 4; kk++) {
            const int kb = kk * 8;
            uint32_t a[2][4];
#pragma unroll
            for (int mi = 0; mi < 2; mi++) {
                const int row = wm * 32 + mi * 16 + grp;
                const uint32_t* as = (const uint32_t*)As;
                a[mi][0] = as[row * 36 + kb + qid];
                a[mi][1] = as[(row + 8) * 36 + kb + qid];
                a[mi][2] = as[row * 36 + kb + qid + 4];
                a[mi][3] = as[(row + 8) * 36 + kb + qid + 4];
            }
            uint32_t b[8][2];
#pragma unroll
            for (int ni = 0; ni < 8; ni++) {
                const int col = wn * 64 + ni * 8 + grp;
                const uint32_t* bs = (const uint32_t*)Bs;
                b[ni][0] = bs[col * 36 + kb + qid];
                b[ni][1] = bs[col * 36 + kb + qid + 4];
            }
#pragma unroll
            for (int mi = 0; mi < 2; mi++)
#pragma unroll
                for (int ni = 0; ni < 8; ni++)
                    mma_tf32(acc[mi][ni], a[mi], b[ni]);
        }
        __syncthreads();
    }

    // Epilogue: c.x=(r,c) c.y=(r,c+1) c.z=(r+8,c) c.w=(r+8,c+1)
#pragma unroll
    for (int mi = 0; mi < 2; mi++) {
#pragma unroll
        for (int half = 0; half < 2; half++) {
            const int m = m0 + wm * 32 + mi * 16 + grp + half * 8;
            if (m >= M) continue;
            int b_idx = 0, itok = 0;
            if (MODE == 0) { b_idx = m / NN; itok = m - b_idx * NN; }
#pragma unroll
            for (int ni = 0; ni < 8; ni++) {
                const float2 cv = (half == 0)
                    ? make_float2(acc[mi][ni].x, acc[mi][ni].y)
                    : make_float2(acc[mi][ni].z, acc[mi][ni].w);
#pragma unroll
                for (int e = 0; e < 2; e++) {
                    const int n = n0 + wn * 64 + ni * 8 + qid * 2 + e;
                    const float val = (e == 0 ? cv.x : cv.y) + bias[n];
                    if (MODE == 1) {
                        Cout[(size_t)m * Nn + n] = val;
                    } else {
                        const int which = n >> 10;      // 0=q 1=k 2=v
                        const int c = n & 1023;
                        const int h = c >> 6;
                        const int d = c & 63;
                        const size_t dst = ((size_t)(b_idx * HH + h)) * NN * HD
                                         + (size_t)itok * HD + d;
                        if (which == 0)      g_q[dst] = val * QSCALE;
                        else if (which == 1) g_k[dst] = val;
                        else                 g_v[dst] = val;
                    }
                }
            }
        }
    }
}

// ---------------------------------------------------------------------------
// cls-token attention: one block per (b,h). q row 0 attends to all N keys.
// ---------------------------------------------------------------------------
__global__ void __launch_bounds__(256)
cls_attn_kernel(const int* __restrict__ tok_mask)
{
    __shared__ float qs[64];
    __shared__ float p[NN];
    __shared__ float red[256];
    __shared__ float part[4 * 64];

    const int bh = blockIdx.x;
    const int b = bh >> 4, h = bh & 15;
    const int tid = threadIdx.x;
    const size_t base = (size_t)bh * NN * HD;

    if (tid < 64) qs[tid] = g_q[base + tid];
    __syncthreads();

    float mx = -1e30f;
    for (int j = tid; j < NN; j += 256) {
        const float* kr = &g_k[base + (size_t)j * HD];
        float acc = 0.f;
#pragma unroll
        for (int d = 0; d < 64; d++) acc = fmaf(qs[d], kr[d], acc);
        if (!tok_mask[b * NN + j]) acc = -1e30f;
        p[j] = acc;
        mx = fmaxf(mx, acc);
    }
    red[tid] = mx;
    __syncthreads();
    for (int s = 128; s; s >>= 1) {
        if (tid < s) red[tid] = fmaxf(red[tid], red[tid + s]);
        __syncthreads();
    }
    mx = red[0];
    __syncthreads();

    float sum = 0.f;
    for (int j = tid; j < NN; j += 256) {
        const float e = __expf(p[j] - mx);
        p[j] = e;
        sum += e;
    }
    red[tid] = sum;
    __syncthreads();
    for (int s = 128; s; s >>= 1) {
        if (tid < s) red[tid] += red[tid + s];
        __syncthreads();
    }
    const float inv = 1.f / red[0];

    const int pt = tid >> 6;      // 0..3
    const int d = tid & 63;
    float acc = 0.f;
    for (int j = pt; j < NN; j += 4)
        acc = fmaf(p[j], g_v[base + (size_t)j * HD + d], acc);
    part[pt * 64 + d] = acc;
    __syncthreads();
    if (tid < 64) {
        const float o = (part[tid] + part[64 + tid] + part[128 + tid] + part[192 + tid]) * inv;
        g_attn[(size_t)b * NN * DIM + (size_t)h * HD + tid] = o;
    }
}

// ---------------------------------------------------------------------------
// Divided (spatial) attention: grid (1024 groups, 7 query chunks of 32).
// Per group: Q chunk (<=32 x 64), K/V (197 x 64) staged in padded smem.
// ---------------------------------------------------------------------------
#define DIV_SMEM_FLOATS (32*64 + 2*197*65 + 32*197 + 197)
#define DIV_SMEM_BYTES  (DIV_SMEM_FLOATS * 4)

__global__ void __launch_bounds__(256)
divided_attn_kernel(const int* __restrict__ tok_mask)
{
    extern __shared__ float sm[];
    float* Qs = sm;                    // 32*64
    float* Ks = Qs + 32 * 64;          // 197*65 (padded)
    float* Vs = Ks + 197 * 65;         // 197*65 (padded)
    float* S  = Vs + 197 * 65;         // 32*197
    float* Ms = S + 32 * 197;          // 197 additive mask

    const int g = blockIdx.x;
    const int bh = g >> 4;
    const int fi = g & 15;
    const int b = bh >> 4;
    const int h = bh & 15;
    const int i0 = blockIdx.y * 32;
    const int cnt = min(32, NS - i0);
    const int tid = threadIdx.x;

    const size_t base = (size_t)bh * NN * HD;
    const int tq0 = 1 + fi * NS + i0;

    for (int idx = tid; idx < cnt * 64; idx += 256) {
        const int i = idx >> 6, d = idx & 63;
        Qs[idx] = g_q[base + (size_t)(tq0 + i) * HD + d];
    }
    for (int idx = tid; idx < 197 * 64; idx += 256) {
        const int j = idx >> 6, d = idx & 63;
        const int tk = (j == 0) ? 0 : (1 + fi * NS + j - 1);
        Ks[j * 65 + d] = g_k[base + (size_t)tk * HD + d];
        Vs[j * 65 + d] = g_v[base + (size_t)tk * HD + d];
    }
    for (int j = tid; j < 197; j += 256) {
        const int tk = (j == 0) ? 0 : (1 + fi * NS + j - 1);
        Ms[j] = tok_mask[b * NN + tk] ? 0.f : -1e30f;
    }
    __syncthreads();

    // S = Q K^T (+mask)
    for (int idx = tid; idx < cnt * 197; idx += 256) {
        const int i = idx / 197;
        const int j = idx - i * 197;
        const float* qr = Qs + i * 64;
        const float* kr = Ks + j * 65;
        float acc = 0.f;
#pragma unroll
        for (int d = 0; d < 64; d++) acc = fmaf(qr[d], kr[d], acc);
        S[idx] = acc + Ms[j];
    }
    __syncthreads();

    // row softmax
    const int w = tid >> 5, lane = tid & 31;
    for (int r = w; r < cnt; r += 8) {
        float* row = S + r * 197;
        float mx = -1e30f;
        for (int j = lane; j < 197; j += 32) mx = fmaxf(mx, row[j]);
        for (int o = 16; o; o >>= 1) mx = fmaxf(mx, __shfl_xor_sync(~0u, mx, o));
        float sum = 0.f;
        for (int j = lane; j < 197; j += 32) {
            const float e = __expf(row[j] - mx);
            row[j] = e;
            sum += e;
        }
        for (int o = 16; o; o >>= 1) sum += __shfl_xor_sync(~0u, sum, o);
        const float inv = 1.f / sum;
        for (int j = lane; j < 197; j += 32) row[j] *= inv;
    }
    __syncthreads();

    // O = P V
    for (int idx = tid; idx < cnt * 64; idx += 256) {
        const int i = idx >> 6, d = idx & 63;
        const float* pr = S + i * 197;
        const float* vc = Vs + d;
        float acc = 0.f;
#pragma unroll 4
        for (int j = 0; j < 197; j++) acc = fmaf(pr[j], vc[j * 65], acc);
        g_attn[(size_t)b * NN * DIM + (size_t)(tq0 + i) * DIM + h * HD + d] = acc;
    }
}

// ---------------------------------------------------------------------------
extern "C" void kernel_launch(void* const* d_in, const int* in_sizes, int n_in,
                              void* d_out, int out_size)
{
    const float* x      = (const float*)d_in[0];
    const float* qkv_w  = (const float*)d_in[1];
    const float* qkv_b  = (const float*)d_in[2];
    const float* proj_w = (const float*)d_in[3];
    const float* proj_b = (const float*)d_in[4];
    const int*   tmask  = (const int*)d_in[5];
    float* out = (float*)d_out;

    cudaFuncSetAttribute((const void*)divided_attn_kernel,
                         cudaFuncAttributeMaxDynamicSharedMemorySize, DIV_SMEM_BYTES);

    // 1) QKV GEMM (tf32 tensor cores; epilogue scatters into head-major q/k/v)
    gemm_tf32_kernel<0><<<dim3(3 * DIM / 128, (M_TOT + 127) / 128), 256>>>(
        x, qkv_w, qkv_b, nullptr, M_TOT, 3 * DIM, DIM);

    // 2) cls attention (64 head-batches)
    cls_attn_kernel<<<BH, 256>>>(tmask);

    // 3) divided spatial attention (1024 groups x 7 query chunks)
    divided_attn_kernel<<<dim3(BH * FF, (NS + 31) / 32), 256, DIV_SMEM_BYTES>>>(tmask);

    // 4) output projection GEMM (tf32 tensor cores)
    gemm_tf32_kernel<1><<<dim3(DIM / 128, (M_TOT + 127) / 128), 256>>>(
        nullptr, proj_w, proj_b, out, M_TOT, DIM, DIM);
}